// round 15
// baseline (speedup 1.0000x reference)
#include <cuda_runtime.h>
#include <cstdint>
#include <math.h>

#define D_MODEL  2048
#define N_HEADS  16
#define HEAD_DIM 128
#define BATCH    2
#define SEQ      2048
#define NTOK     (BATCH * SEQ)
#define KVSPLIT  4
#define KCHUNK   (D_MODEL / KVSPLIT)   // 512
#define KVN      256                   // combined K|V output width

__device__ float    g_q   [NTOK * D_MODEL];
__device__ uint32_t g_kt  [NTOK * HEAD_DIM];          // K, tf32 bits [token][d]
__device__ uint32_t g_vt  [HEAD_DIM * NTOK];          // V^T, tf32 bits [d][token]
__device__ float    g_ao  [NTOK * D_MODEL];
__device__ uint32_t g_wqt [D_MODEL * D_MODEL];        // Wq^T tf32 [N][K]
__device__ uint32_t g_wot [D_MODEL * D_MODEL];        // Wo^T tf32 [N][K]
__device__ uint32_t g_wkvt[KVN * D_MODEL];            // (Wk|Wv)^T tf32 [256][2048]
__device__ float    g_kvp [KVSPLIT][NTOK * KVN];      // split-K partials

// ---------------------------------------------------------------------------
// Helpers
// ---------------------------------------------------------------------------
__device__ __forceinline__ uint32_t f2tf32(float x) {
    uint32_t r;
    asm("cvt.rna.tf32.f32 %0, %1;" : "=r"(r) : "f"(x));
    return r;
}

__device__ __forceinline__ void mma_tf32(float* d,
    uint32_t a0, uint32_t a1, uint32_t a2, uint32_t a3,
    uint32_t b0, uint32_t b1)
{
    asm volatile(
        "mma.sync.aligned.m16n8k8.row.col.f32.tf32.tf32.f32 "
        "{%0,%1,%2,%3},{%4,%5,%6,%7},{%8,%9},{%0,%1,%2,%3};"
        : "+f"(d[0]), "+f"(d[1]), "+f"(d[2]), "+f"(d[3])
        : "r"(a0), "r"(a1), "r"(a2), "r"(a3), "r"(b0), "r"(b1));
}

__device__ __forceinline__ void ldsm_x4(uint32_t& r0, uint32_t& r1,
                                        uint32_t& r2, uint32_t& r3,
                                        uint32_t addr)
{
    asm volatile("ldmatrix.sync.aligned.m8n8.x4.shared.b16 {%0,%1,%2,%3}, [%4];"
                 : "=r"(r0), "=r"(r1), "=r"(r2), "=r"(r3) : "r"(addr));
}

// ---------------------------------------------------------------------------
// Generic transpose + tf32-convert: dst[rowOff + n][k] = tf32(src[k][n]).
// ---------------------------------------------------------------------------
__global__ __launch_bounds__(256) void transpose_kn(
    const float* __restrict__ src, uint32_t* __restrict__ dst,
    int srcCols, int rowOff)
{
    __shared__ uint32_t tile[32][33];
    int x = blockIdx.x * 32 + threadIdx.x;
    int y = blockIdx.y * 32 + threadIdx.y;
#pragma unroll
    for (int j = 0; j < 32; j += 8)
        tile[threadIdx.y + j][threadIdx.x] =
            f2tf32(src[(size_t)(y + j) * srcCols + x]);
    __syncthreads();
    int nx = blockIdx.y * 32 + threadIdx.x;
    int ny = rowOff + blockIdx.x * 32 + threadIdx.y;
#pragma unroll
    for (int j = 0; j < 32; j += 8)
        dst[(size_t)(ny + j) * D_MODEL + nx] = tile[threadIdx.x][threadIdx.y + j];
}

// ---------------------------------------------------------------------------
// TF32 GEMM (ldmatrix). C = A @ Bt^T + bias.  (unchanged from R12)
// ---------------------------------------------------------------------------
#define GBM 128
#define GBN 128
#define GBK 32
#define ASTR 36
#define BSTR2 36

__global__ __launch_bounds__(256, 2) void tf32_gemm_bias(
    int M, int N, int K,
    const float* __restrict__ A,
    const uint32_t* __restrict__ Bt,
    const float* __restrict__ bias,
    float* __restrict__ C)
{
    __shared__ uint32_t As[GBM * ASTR];
    __shared__ uint32_t Bs[GBN * BSTR2];

    const int tid  = threadIdx.x;
    const int wid  = tid >> 5;
    const int lane = tid & 31;
    const int g    = lane >> 2;
    const int t4   = lane & 3;
    const int wm   = (wid >> 2) * 64;
    const int wn   = (wid & 3) * 32;

    const float*    Ab = A  + (size_t)blockIdx.y * GBM * K;
    const uint32_t* Bb = Bt + (size_t)blockIdx.x * GBN * K;

    const int lrow = tid >> 3;
    const int lcol = (tid & 7) * 4;

    const int a_row = (lane & 7) + ((lane >> 3) & 1) * 8;
    const int a_kh  = ((lane >> 4) & 1) * 4;
    const int b_row = (lane & 7) + ((lane >> 4) & 1) * 8;
    const int b_kh  = ((lane >> 3) & 1) * 4;

    const uint32_t As_b = (uint32_t)__cvta_generic_to_shared(As);
    const uint32_t Bs_b = (uint32_t)__cvta_generic_to_shared(Bs);

    float acc[4][4][4];
#pragma unroll
    for (int mi = 0; mi < 4; mi++)
#pragma unroll
        for (int ni = 0; ni < 4; ni++)
#pragma unroll
            for (int r = 0; r < 4; r++) acc[mi][ni][r] = 0.0f;

    for (int k0 = 0; k0 < K; k0 += GBK) {
#pragma unroll
        for (int i = 0; i < 4; i++) {
            int row = lrow + 32 * i;
            float4 a = *(const float4*)&Ab[(size_t)row * K + k0 + lcol];
            uint4 u = make_uint4(f2tf32(a.x), f2tf32(a.y), f2tf32(a.z), f2tf32(a.w));
            *(uint4*)&As[row * ASTR + lcol] = u;
        }
#pragma unroll
        for (int i = 0; i < 4; i++) {
            int row = lrow + 32 * i;
            uint4 u = *(const uint4*)&Bb[(size_t)row * K + k0 + lcol];
            *(uint4*)&Bs[row * BSTR2 + lcol] = u;
        }
        __syncthreads();

#pragma unroll
        for (int ks = 0; ks < 4; ks++) {
            uint32_t a[4][4];
#pragma unroll
            for (int mi = 0; mi < 4; mi++) {
                uint32_t addr = As_b +
                    ((wm + mi * 16 + a_row) * ASTR + ks * 8 + a_kh) * 4;
                ldsm_x4(a[mi][0], a[mi][1], a[mi][2], a[mi][3], addr);
            }
            uint32_t bf[2][4];
#pragma unroll
            for (int p = 0; p < 2; p++) {
                uint32_t addr = Bs_b +
                    ((wn + p * 16 + b_row) * BSTR2 + ks * 8 + b_kh) * 4;
                ldsm_x4(bf[p][0], bf[p][1], bf[p][2], bf[p][3], addr);
            }
#pragma unroll
            for (int p = 0; p < 2; p++)
#pragma unroll
                for (int hh = 0; hh < 2; hh++) {
                    const int ni = p * 2 + hh;
#pragma unroll
                    for (int mi = 0; mi < 4; mi++)
                        mma_tf32(acc[mi][ni],
                                 a[mi][0], a[mi][1], a[mi][2], a[mi][3],
                                 bf[p][hh * 2], bf[p][hh * 2 + 1]);
                }
        }
        __syncthreads();
    }

    const int rowBase = blockIdx.y * GBM + wm;
    const int colBase = blockIdx.x * GBN + wn;
#pragma unroll
    for (int mi = 0; mi < 4; mi++) {
#pragma unroll
        for (int ni = 0; ni < 4; ni++) {
            const int col = colBase + ni * 8 + 2 * t4;
            const int r0  = rowBase + mi * 16 + g;
            float2 v0, v1;
            v0.x = acc[mi][ni][0] + bias[col];
            v0.y = acc[mi][ni][1] + bias[col + 1];
            v1.x = acc[mi][ni][2] + bias[col];
            v1.y = acc[mi][ni][3] + bias[col + 1];
            *(float2*)&C[(size_t)r0 * N + col]       = v0;
            *(float2*)&C[(size_t)(r0 + 8) * N + col] = v1;
        }
    }
}

// ---------------------------------------------------------------------------
// K/V projection: TF32 MMA, split-K (unchanged).
// ---------------------------------------------------------------------------
__global__ __launch_bounds__(256, 2) void kv_gemm_splitk(
    const float* __restrict__ A,
    const uint32_t* __restrict__ Bt,
    float* __restrict__ Cp)
{
    __shared__ uint32_t As[GBM * ASTR];
    __shared__ uint32_t Bs[GBN * BSTR2];

    const int tid  = threadIdx.x;
    const int wid  = tid >> 5;
    const int lane = tid & 31;
    const int g    = lane >> 2;
    const int t4   = lane & 3;
    const int wm   = (wid >> 2) * 64;
    const int wn   = (wid & 3) * 32;

    const float*    Ab = A  + (size_t)blockIdx.y * GBM * D_MODEL;
    const uint32_t* Bb = Bt + (size_t)blockIdx.x * GBN * D_MODEL;
    float*          Cb = Cp + (size_t)blockIdx.z * NTOK * KVN;

    const int lrow = tid >> 3;
    const int lcol = (tid & 7) * 4;

    const int a_row = (lane & 7) + ((lane >> 3) & 1) * 8;
    const int a_kh  = ((lane >> 4) & 1) * 4;
    const int b_row = (lane & 7) + ((lane >> 4) & 1) * 8;
    const int b_kh  = ((lane >> 3) & 1) * 4;

    const uint32_t As_b = (uint32_t)__cvta_generic_to_shared(As);
    const uint32_t Bs_b = (uint32_t)__cvta_generic_to_shared(Bs);

    float acc[4][4][4];
#pragma unroll
    for (int mi = 0; mi < 4; mi++)
#pragma unroll
        for (int ni = 0; ni < 4; ni++)
#pragma unroll
            for (int r = 0; r < 4; r++) acc[mi][ni][r] = 0.0f;

    const int kbeg = blockIdx.z * KCHUNK;
    for (int k0 = kbeg; k0 < kbeg + KCHUNK; k0 += GBK) {
#pragma unroll
        for (int i = 0; i < 4; i++) {
            int row = lrow + 32 * i;
            float4 a = *(const float4*)&Ab[(size_t)row * D_MODEL + k0 + lcol];
            uint4 u = make_uint4(f2tf32(a.x), f2tf32(a.y), f2tf32(a.z), f2tf32(a.w));
            *(uint4*)&As[row * ASTR + lcol] = u;
        }
#pragma unroll
        for (int i = 0; i < 4; i++) {
            int row = lrow + 32 * i;
            uint4 u = *(const uint4*)&Bb[(size_t)row * D_MODEL + k0 + lcol];
            *(uint4*)&Bs[row * BSTR2 + lcol] = u;
        }
        __syncthreads();

#pragma unroll
        for (int ks = 0; ks < 4; ks++) {
            uint32_t a[4][4];
#pragma unroll
            for (int mi = 0; mi < 4; mi++) {
                uint32_t addr = As_b +
                    ((wm + mi * 16 + a_row) * ASTR + ks * 8 + a_kh) * 4;
                ldsm_x4(a[mi][0], a[mi][1], a[mi][2], a[mi][3], addr);
            }
            uint32_t bf[2][4];
#pragma unroll
            for (int p = 0; p < 2; p++) {
                uint32_t addr = Bs_b +
                    ((wn + p * 16 + b_row) * BSTR2 + ks * 8 + b_kh) * 4;
                ldsm_x4(bf[p][0], bf[p][1], bf[p][2], bf[p][3], addr);
            }
#pragma unroll
            for (int p = 0; p < 2; p++)
#pragma unroll
                for (int hh = 0; hh < 2; hh++) {
                    const int ni = p * 2 + hh;
#pragma unroll
                    for (int mi = 0; mi < 4; mi++)
                        mma_tf32(acc[mi][ni],
                                 a[mi][0], a[mi][1], a[mi][2], a[mi][3],
                                 bf[p][hh * 2], bf[p][hh * 2 + 1]);
                }
        }
        __syncthreads();
    }

    const int rowBase = blockIdx.y * GBM + wm;
    const int colBase = blockIdx.x * GBN + wn;
#pragma unroll
    for (int mi = 0; mi < 4; mi++) {
#pragma unroll
        for (int ni = 0; ni < 4; ni++) {
            const int col = colBase + ni * 8 + 2 * t4;
            const int r0  = rowBase + mi * 16 + g;
            *(float2*)&Cb[(size_t)r0 * KVN + col] =
                make_float2(acc[mi][ni][0], acc[mi][ni][1]);
            *(float2*)&Cb[(size_t)(r0 + 8) * KVN + col] =
                make_float2(acc[mi][ni][2], acc[mi][ni][3]);
        }
    }
}

// ---------------------------------------------------------------------------
// Reduce partials + bias. cols 0..127 -> K tf32 bits; 128..255 -> Vt tf32 bits.
// ---------------------------------------------------------------------------
__global__ __launch_bounds__(256) void kv_reduce_t(
    const float* __restrict__ Cp,
    const float* __restrict__ bk, const float* __restrict__ bv,
    uint32_t* __restrict__ Kout, uint32_t* __restrict__ Vt)
{
    __shared__ float tile[32][33];
    const int col0 = blockIdx.x * 32;
    const int tok0 = blockIdx.y * 32;
    const int tx = threadIdx.x, ty = threadIdx.y;
    const int col = col0 + tx;
    const bool isK = (col0 < HEAD_DIM);
    const float bias = isK ? bk[col] : bv[col - HEAD_DIM];

#pragma unroll
    for (int j = 0; j < 32; j += 8) {
        const int tok = tok0 + ty + j;
        float s = bias;
#pragma unroll
        for (int z = 0; z < KVSPLIT; z++)
            s += Cp[(size_t)z * NTOK * KVN + (size_t)tok * KVN + col];
        if (isK) Kout[(size_t)tok * HEAD_DIM + col] = f2tf32(s);
        else     tile[ty + j][tx] = s;
    }
    if (!isK) {
        __syncthreads();
#pragma unroll
        for (int j = 0; j < 32; j += 8)
            Vt[(size_t)(col0 - HEAD_DIM + ty + j) * NTOK + tok0 + tx] =
                f2tf32(tile[tx][ty + j]);
    }
}

// ---------------------------------------------------------------------------
// TF32 MMA flash attention, deferred-PV pipeline:
//   scores(t) -> PV(t-1) -> softmax(t).  Q fragments live in registers
//   (aq[16][4]); V double-buffered; K single-stage; 2 CTAs/SM.
// ---------------------------------------------------------------------------
#define AQ 64
#define AK 64
#define QP 132
#define KP 132
#define VP2 68
#define KW  (AK * KP)          // 8448 words
#define VW  (HEAD_DIM * VP2)   // 8704 words
#define NIT (SEQ / AK)         // 32

__global__ __launch_bounds__(128, 2) void mqa_attn_tf32(
    const float* __restrict__ Q,
    const uint32_t* __restrict__ Kg,     // tf32 bits [token][128]
    const uint32_t* __restrict__ Vtg,    // tf32 bits [d][NTOK]
    const int* __restrict__ mask,
    float* __restrict__ Og)
{
    extern __shared__ uint32_t sm_u[];
    uint32_t* Ks   = sm_u;               // KW
    uint32_t* Vts0 = sm_u + KW;          // VW (also Q staging in prologue)
    uint32_t* Vts1 = Vts0 + VW;          // VW
    float*   sbias = (float*)(Vts1 + VW);

    const int tid  = threadIdx.x;
    const int wid  = tid >> 5;           // 0..3
    const int lane = tid & 31;
    const int g    = lane >> 2;
    const int t4   = lane & 3;
    const int b  = blockIdx.z, h = blockIdx.y;
    const int q0 = blockIdx.x * AQ;
    const int wrow = wid * 16;

    const int a_row = (lane & 7) + ((lane >> 3) & 1) * 8;
    const int a_kh  = ((lane >> 4) & 1) * 4;
    const int b_row = (lane & 7) + ((lane >> 4) & 1) * 8;
    const int b_kh  = ((lane >> 3) & 1) * 4;
    const uint32_t Ks_b = (uint32_t)__cvta_generic_to_shared(Ks);
    const uint32_t Vb0  = (uint32_t)__cvta_generic_to_shared(Vts0);
    const uint32_t Vb1  = (uint32_t)__cvta_generic_to_shared(Vts1);

    const uint32_t* Kgb  = Kg  + (size_t)(b * SEQ) * HEAD_DIM;
    const uint32_t* Vtgb = Vtg + (size_t)b * SEQ;

    // staging coords (128 threads)
    const int kpr = tid >> 5;            // K row base (+4u)
    const int kpc = (tid & 31) << 2;     // K word col
    const int vpr = tid >> 4;            // Vt row base (+8u)
    const int vpc = (tid & 15) << 2;     // Vt word col

    // ---- Prologue: Q -> (Vts0 as staging) -> register fragments ----
    const float* Qp = Q + ((size_t)(b * SEQ + q0)) * D_MODEL + h * HEAD_DIM;
    for (int i = tid; i < AQ * HEAD_DIM / 4; i += 128) {
        int r = i >> 5, c = (i & 31) << 2;
        float4 qv = *(const float4*)&Qp[(size_t)r * D_MODEL + c];
        uint4 u = make_uint4(f2tf32(qv.x), f2tf32(qv.y), f2tf32(qv.z), f2tf32(qv.w));
        *(uint4*)&Vts0[r * QP + c] = u;
    }
    __syncthreads();
    uint32_t aq[16][4];
#pragma unroll
    for (int ks = 0; ks < 16; ks++)
        ldsm_x4(aq[ks][0], aq[ks][1], aq[ks][2], aq[ks][3],
                Vb0 + ((wrow + a_row) * QP + ks * 8 + a_kh) * 4);
    // (no sync needed here: mainloop's first sync precedes the Vts0 overwrite)

    float m0 = -1e30f, m1 = -1e30f, l0 = 0.0f, l1 = 0.0f;
    float o[16][4];
#pragma unroll
    for (int n = 0; n < 16; n++)
#pragma unroll
        for (int r = 0; r < 4; r++) o[n][r] = 0.0f;
    uint32_t ptA[8][4];

    const float scale = 0.08838834764831845f;
    const int src1 = (g << 2) + (t4 >> 1);
    const int src2 = src1 + 2;
    const bool odd = (t4 & 1);

    for (int t = 0; t < NIT; t++) {
        const int k0 = t * AK;
        const uint32_t vprev = (t & 1) ? Vb0 : Vb1;
        uint32_t* Vcur = (t & 1) ? Vts1 : Vts0;

        __syncthreads();   // scores(t-1) & PV(t-2) complete; safe to overwrite
        // stage K(t) and V(t) (demand loads)
#pragma unroll
        for (int u = 0; u < 16; u++)
            *(uint4*)&Ks[(kpr + 4 * u) * KP + kpc] =
                *(const uint4*)&Kgb[(size_t)(k0 + kpr + 4 * u) * HEAD_DIM + kpc];
#pragma unroll
        for (int u = 0; u < 16; u++)
            *(uint4*)&Vcur[(vpr + 8 * u) * VP2 + vpc] =
                *(const uint4*)&Vtgb[(size_t)(vpr + 8 * u) * NTOK + k0 + vpc];
        if (tid < AK)
            sbias[tid] = mask[(size_t)b * SEQ + k0 + tid] ? 0.0f : -1e9f;
        __syncthreads();

        // ---- Scores(t): Q frags from registers ----
        float s[8][4];
#pragma unroll
        for (int j = 0; j < 8; j++)
#pragma unroll
            for (int r = 0; r < 4; r++) s[j][r] = 0.0f;

#pragma unroll
        for (int ks = 0; ks < 16; ks++) {
#pragma unroll
            for (int p = 0; p < 4; p++) {
                uint32_t bf[4];
                ldsm_x4(bf[0], bf[1], bf[2], bf[3],
                        Ks_b + ((p * 16 + b_row) * KP + ks * 8 + b_kh) * 4);
                mma_tf32(s[2 * p],     aq[ks][0], aq[ks][1], aq[ks][2], aq[ks][3],
                         bf[0], bf[1]);
                mma_tf32(s[2 * p + 1], aq[ks][0], aq[ks][1], aq[ks][2], aq[ks][3],
                         bf[2], bf[3]);
            }
        }

        // ---- PV(t-1): independent of softmax chain below; ptxas interleaves ----
        if (t > 0) {
#pragma unroll
            for (int j = 0; j < 8; j++) {
#pragma unroll
                for (int p = 0; p < 8; p++) {
                    uint32_t bf[4];
                    ldsm_x4(bf[0], bf[1], bf[2], bf[3],
                            vprev + ((p * 16 + b_row) * VP2 + j * 8 + b_kh) * 4);
                    mma_tf32(o[2 * p],     ptA[j][0], ptA[j][1], ptA[j][2], ptA[j][3],
                             bf[0], bf[1]);
                    mma_tf32(o[2 * p + 1], ptA[j][0], ptA[j][1], ptA[j][2], ptA[j][3],
                             bf[2], bf[3]);
                }
            }
        }

        // ---- softmax(t) ----
        float rmax0 = -1e30f, rmax1 = -1e30f;
#pragma unroll
        for (int j = 0; j < 8; j++) {
            float2 sv = *(float2*)&sbias[j * 8 + 2 * t4];
            s[j][0] = s[j][0] * scale + sv.x;
            s[j][1] = s[j][1] * scale + sv.y;
            s[j][2] = s[j][2] * scale + sv.x;
            s[j][3] = s[j][3] * scale + sv.y;
            rmax0 = fmaxf(rmax0, fmaxf(s[j][0], s[j][1]));
            rmax1 = fmaxf(rmax1, fmaxf(s[j][2], s[j][3]));
        }
#pragma unroll
        for (int off = 1; off <= 2; off <<= 1) {
            rmax0 = fmaxf(rmax0, __shfl_xor_sync(0xffffffffu, rmax0, off));
            rmax1 = fmaxf(rmax1, __shfl_xor_sync(0xffffffffu, rmax1, off));
        }
        const float mn0 = fmaxf(m0, rmax0);
        const float mn1 = fmaxf(m1, rmax1);
        const float c0 = __expf(m0 - mn0);
        const float c1 = __expf(m1 - mn1);
        m0 = mn0; m1 = mn1;

        // rescale o AFTER PV(t-1) has been added (deferred recurrence)
#pragma unroll
        for (int n = 0; n < 16; n++) {
            o[n][0] *= c0; o[n][1] *= c0;
            o[n][2] *= c1; o[n][3] *= c1;
        }

        float rs0 = 0.0f, rs1 = 0.0f;
        uint32_t pt[8][4];
#pragma unroll
        for (int j = 0; j < 8; j++) {
            float p0 = __expf(s[j][0] - mn0);
            float p1 = __expf(s[j][1] - mn0);
            float p2 = __expf(s[j][2] - mn1);
            float p3 = __expf(s[j][3] - mn1);
            rs0 += p0 + p1;
            rs1 += p2 + p3;
            pt[j][0] = f2tf32(p0);
            pt[j][1] = f2tf32(p1);
            pt[j][2] = f2tf32(p2);
            pt[j][3] = f2tf32(p3);
        }
#pragma unroll
        for (int off = 1; off <= 2; off <<= 1) {
            rs0 += __shfl_xor_sync(0xffffffffu, rs0, off);
            rs1 += __shfl_xor_sync(0xffffffffu, rs1, off);
        }
        l0 = l0 * c0 + rs0;
        l1 = l1 * c1 + rs1;

        // assemble A-fragments of P(t) for next iteration's PV
#pragma unroll
        for (int j = 0; j < 8; j++) {
            uint32_t x00 = __shfl_sync(0xffffffffu, pt[j][0], src1);
            uint32_t x01 = __shfl_sync(0xffffffffu, pt[j][1], src1);
            uint32_t x10 = __shfl_sync(0xffffffffu, pt[j][0], src2);
            uint32_t x11 = __shfl_sync(0xffffffffu, pt[j][1], src2);
            uint32_t x20 = __shfl_sync(0xffffffffu, pt[j][2], src1);
            uint32_t x21 = __shfl_sync(0xffffffffu, pt[j][3], src1);
            uint32_t x30 = __shfl_sync(0xffffffffu, pt[j][2], src2);
            uint32_t x31 = __shfl_sync(0xffffffffu, pt[j][3], src2);
            ptA[j][0] = odd ? x01 : x00;
            ptA[j][2] = odd ? x11 : x10;
            ptA[j][1] = odd ? x21 : x20;
            ptA[j][3] = odd ? x31 : x30;
        }
    }

    // ---- final PV(NIT-1): V stage (NIT-1)&1 = 1 ----
#pragma unroll
    for (int j = 0; j < 8; j++) {
#pragma unroll
        for (int p = 0; p < 8; p++) {
            uint32_t bf[4];
            ldsm_x4(bf[0], bf[1], bf[2], bf[3],
                    Vb1 + ((p * 16 + b_row) * VP2 + j * 8 + b_kh) * 4);
            mma_tf32(o[2 * p],     ptA[j][0], ptA[j][1], ptA[j][2], ptA[j][3],
                     bf[0], bf[1]);
            mma_tf32(o[2 * p + 1], ptA[j][0], ptA[j][1], ptA[j][2], ptA[j][3],
                     bf[2], bf[3]);
        }
    }

    // ---- Epilogue ----
    const float inv0 = 1.0f / l0;
    const float inv1 = 1.0f / l1;
    float* Op0 = Og + ((size_t)(b * SEQ + q0 + wrow + g    )) * D_MODEL + h * HEAD_DIM;
    float* Op1 = Og + ((size_t)(b * SEQ + q0 + wrow + g + 8)) * D_MODEL + h * HEAD_DIM;
#pragma unroll
    for (int n = 0; n < 16; n++) {
        const int col = n * 8 + 2 * t4;
        float2 v0, v1;
        v0.x = o[n][0] * inv0; v0.y = o[n][1] * inv0;
        v1.x = o[n][2] * inv1; v1.y = o[n][3] * inv1;
        *(float2*)&Op0[col] = v0;
        *(float2*)&Op1[col] = v1;
    }
}

#define ATTN_SMEM_BYTES ((KW + 2 * VW) * 4 + AK * 4)

// ---------------------------------------------------------------------------
extern "C" void kernel_launch(void* const* d_in, const int* in_sizes, int n_in,
                              void* d_out, int out_size)
{
    const float* x    = (const float*)d_in[0];
    const int*   mask = (const int*)d_in[1];
    const float* Wq   = (const float*)d_in[2];
    const float* bq   = (const float*)d_in[3];
    const float* Wk   = (const float*)d_in[4];
    const float* bk   = (const float*)d_in[5];
    const float* Wv   = (const float*)d_in[6];
    const float* bv   = (const float*)d_in[7];
    const float* Wo   = (const float*)d_in[8];
    const float* bo   = (const float*)d_in[9];
    float* out = (float*)d_out;

    float *q, *ao, *kvp;
    uint32_t *kt, *vt, *wqt, *wot, *wkvt;
    cudaGetSymbolAddress((void**)&q,    g_q);
    cudaGetSymbolAddress((void**)&kt,   g_kt);
    cudaGetSymbolAddress((void**)&vt,   g_vt);
    cudaGetSymbolAddress((void**)&ao,   g_ao);
    cudaGetSymbolAddress((void**)&kvp,  g_kvp);
    cudaGetSymbolAddress((void**)&wqt,  g_wqt);
    cudaGetSymbolAddress((void**)&wot,  g_wot);
    cudaGetSymbolAddress((void**)&wkvt, g_wkvt);

    // Weight transposes (tf32)
    transpose_kn<<<dim3(64, 64), dim3(32, 8)>>>(Wq, wqt, D_MODEL, 0);
    transpose_kn<<<dim3(64, 64), dim3(32, 8)>>>(Wo, wot, D_MODEL, 0);
    transpose_kn<<<dim3(4, 64),  dim3(32, 8)>>>(Wk, wkvt, HEAD_DIM, 0);
    transpose_kn<<<dim3(4, 64),  dim3(32, 8)>>>(Wv, wkvt, HEAD_DIM, HEAD_DIM);

    // Q projection
    tf32_gemm_bias<<<dim3(D_MODEL / GBN, NTOK / GBM), 256>>>(
        NTOK, D_MODEL, D_MODEL, x, wqt, bq, q);

    // K/V projection: tf32 split-K MMA + reduce (both outputs tf32 bits)
    kv_gemm_splitk<<<dim3(KVN / GBN, NTOK / GBM, KVSPLIT), 256>>>(x, wkvt, kvp);
    kv_reduce_t<<<dim3(KVN / 32, NTOK / 32), dim3(32, 8)>>>(kvp, bk, bv, kt, vt);

    // Attention (deferred-PV pipeline, 2 CTAs/SM)
    cudaFuncSetAttribute(mqa_attn_tf32,
                         cudaFuncAttributeMaxDynamicSharedMemorySize,
                         ATTN_SMEM_BYTES);
    mqa_attn_tf32<<<dim3(SEQ / AQ, N_HEADS, BATCH), 128, ATTN_SMEM_BYTES>>>(
        q, kt, vt, mask, ao);

    // Output projection
    tf32_gemm_bias<<<dim3(D_MODEL / GBN, NTOK / GBM), 256>>>(
        NTOK, D_MODEL, D_MODEL, ao, wot, bo, out);
}

// round 16
// speedup vs baseline: 1.0899x; 1.0899x over previous
#include <cuda_runtime.h>
#include <cstdint>
#include <math.h>

#define D_MODEL  2048
#define N_HEADS  16
#define HEAD_DIM 128
#define BATCH    2
#define SEQ      2048
#define NTOK     (BATCH * SEQ)
#define KVN      256                   // combined K|V width
#define NQKV     (D_MODEL + KVN)       // 2304 fused output width

__device__ float    g_q    [NTOK * D_MODEL];
__device__ float    g_kvf  [NTOK * KVN];              // fused K|V output (bias incl.)
__device__ uint32_t g_kt   [NTOK * HEAD_DIM];         // K, tf32 bits [token][d]
__device__ uint32_t g_vt   [HEAD_DIM * NTOK];         // V^T, tf32 bits [d][token]
__device__ float    g_ao   [NTOK * D_MODEL];
__device__ uint32_t g_wqkvt[NQKV * D_MODEL];          // (Wq|Wk|Wv)^T tf32 [2304][2048]
__device__ uint32_t g_wot  [D_MODEL * D_MODEL];       // Wo^T tf32 [N][K]
__device__ float    g_bqkv [NQKV];                    // combined bias

// ---------------------------------------------------------------------------
// Helpers
// ---------------------------------------------------------------------------
__device__ __forceinline__ uint32_t f2tf32(float x) {
    uint32_t r;
    asm("cvt.rna.tf32.f32 %0, %1;" : "=r"(r) : "f"(x));
    return r;
}

__device__ __forceinline__ void mma_tf32(float* d,
    uint32_t a0, uint32_t a1, uint32_t a2, uint32_t a3,
    uint32_t b0, uint32_t b1)
{
    asm volatile(
        "mma.sync.aligned.m16n8k8.row.col.f32.tf32.tf32.f32 "
        "{%0,%1,%2,%3},{%4,%5,%6,%7},{%8,%9},{%0,%1,%2,%3};"
        : "+f"(d[0]), "+f"(d[1]), "+f"(d[2]), "+f"(d[3])
        : "r"(a0), "r"(a1), "r"(a2), "r"(a3), "r"(b0), "r"(b1));
}

__device__ __forceinline__ void ldsm_x4(uint32_t& r0, uint32_t& r1,
                                        uint32_t& r2, uint32_t& r3,
                                        uint32_t addr)
{
    asm volatile("ldmatrix.sync.aligned.m8n8.x4.shared.b16 {%0,%1,%2,%3}, [%4];"
                 : "=r"(r0), "=r"(r1), "=r"(r2), "=r"(r3) : "r"(addr));
}

// ---------------------------------------------------------------------------
// Generic transpose + tf32-convert: dst[rowOff + n][k] = tf32(src[k][n]).
// dst row stride = D_MODEL.
// ---------------------------------------------------------------------------
__global__ __launch_bounds__(256) void transpose_kn(
    const float* __restrict__ src, uint32_t* __restrict__ dst,
    int srcCols, int rowOff)
{
    __shared__ uint32_t tile[32][33];
    int x = blockIdx.x * 32 + threadIdx.x;
    int y = blockIdx.y * 32 + threadIdx.y;
#pragma unroll
    for (int j = 0; j < 32; j += 8)
        tile[threadIdx.y + j][threadIdx.x] =
            f2tf32(src[(size_t)(y + j) * srcCols + x]);
    __syncthreads();
    int nx = blockIdx.y * 32 + threadIdx.x;
    int ny = rowOff + blockIdx.x * 32 + threadIdx.y;
#pragma unroll
    for (int j = 0; j < 32; j += 8)
        dst[(size_t)(ny + j) * D_MODEL + nx] = tile[threadIdx.x][threadIdx.y + j];
}

// Assemble combined bias [bq | bk | bv]
__global__ __launch_bounds__(256) void build_bias(
    const float* __restrict__ bq, const float* __restrict__ bk,
    const float* __restrict__ bv, float* __restrict__ dst)
{
    int i = blockIdx.x * 256 + threadIdx.x;
    if (i < D_MODEL)                 dst[i] = bq[i];
    else if (i < D_MODEL + HEAD_DIM) dst[i] = bk[i - D_MODEL];
    else if (i < NQKV)               dst[i] = bv[i - D_MODEL - HEAD_DIM];
}

// ---------------------------------------------------------------------------
// Fused QKV GEMM: grid (NQKV/128 = 18, NTOK/128 = 32).
// Block cols 0..15 -> Q (+bias) in g_q; cols 16..17 -> g_kvf (+bias).
// Body identical to the proven ldmatrix tf32 GEMM.
// ---------------------------------------------------------------------------
#define GBM 128
#define GBN 128
#define GBK 32
#define ASTR 36
#define BSTR2 36

__global__ __launch_bounds__(256, 2) void qkv_gemm_fused(
    const float* __restrict__ A,
    const uint32_t* __restrict__ Bt,     // [2304][2048] tf32
    const float* __restrict__ bias,      // [2304]
    float* __restrict__ CQ,              // [NTOK][2048]
    float* __restrict__ CKV)             // [NTOK][256]
{
    __shared__ uint32_t As[GBM * ASTR];
    __shared__ uint32_t Bs[GBN * BSTR2];

    const int tid  = threadIdx.x;
    const int wid  = tid >> 5;
    const int lane = tid & 31;
    const int g    = lane >> 2;
    const int t4   = lane & 3;
    const int wm   = (wid >> 2) * 64;
    const int wn   = (wid & 3) * 32;

    const float*    Ab = A  + (size_t)blockIdx.y * GBM * D_MODEL;
    const uint32_t* Bb = Bt + (size_t)blockIdx.x * GBN * D_MODEL;

    const int lrow = tid >> 3;
    const int lcol = (tid & 7) * 4;

    const int a_row = (lane & 7) + ((lane >> 3) & 1) * 8;
    const int a_kh  = ((lane >> 4) & 1) * 4;
    const int b_row = (lane & 7) + ((lane >> 4) & 1) * 8;
    const int b_kh  = ((lane >> 3) & 1) * 4;

    const uint32_t As_b = (uint32_t)__cvta_generic_to_shared(As);
    const uint32_t Bs_b = (uint32_t)__cvta_generic_to_shared(Bs);

    float acc[4][4][4];
#pragma unroll
    for (int mi = 0; mi < 4; mi++)
#pragma unroll
        for (int ni = 0; ni < 4; ni++)
#pragma unroll
            for (int r = 0; r < 4; r++) acc[mi][ni][r] = 0.0f;

    for (int k0 = 0; k0 < D_MODEL; k0 += GBK) {
#pragma unroll
        for (int i = 0; i < 4; i++) {
            int row = lrow + 32 * i;
            float4 a = *(const float4*)&Ab[(size_t)row * D_MODEL + k0 + lcol];
            uint4 u = make_uint4(f2tf32(a.x), f2tf32(a.y), f2tf32(a.z), f2tf32(a.w));
            *(uint4*)&As[row * ASTR + lcol] = u;
        }
#pragma unroll
        for (int i = 0; i < 4; i++) {
            int row = lrow + 32 * i;
            uint4 u = *(const uint4*)&Bb[(size_t)row * D_MODEL + k0 + lcol];
            *(uint4*)&Bs[row * BSTR2 + lcol] = u;
        }
        __syncthreads();

#pragma unroll
        for (int ks = 0; ks < 4; ks++) {
            uint32_t a[4][4];
#pragma unroll
            for (int mi = 0; mi < 4; mi++) {
                uint32_t addr = As_b +
                    ((wm + mi * 16 + a_row) * ASTR + ks * 8 + a_kh) * 4;
                ldsm_x4(a[mi][0], a[mi][1], a[mi][2], a[mi][3], addr);
            }
            uint32_t bf[2][4];
#pragma unroll
            for (int p = 0; p < 2; p++) {
                uint32_t addr = Bs_b +
                    ((wn + p * 16 + b_row) * BSTR2 + ks * 8 + b_kh) * 4;
                ldsm_x4(bf[p][0], bf[p][1], bf[p][2], bf[p][3], addr);
            }
#pragma unroll
            for (int p = 0; p < 2; p++)
#pragma unroll
                for (int hh = 0; hh < 2; hh++) {
                    const int ni = p * 2 + hh;
#pragma unroll
                    for (int mi = 0; mi < 4; mi++)
                        mma_tf32(acc[mi][ni],
                                 a[mi][0], a[mi][1], a[mi][2], a[mi][3],
                                 bf[p][hh * 2], bf[p][hh * 2 + 1]);
                }
        }
        __syncthreads();
    }

    const int rowBase = blockIdx.y * GBM + wm;
    const int colBase = blockIdx.x * GBN + wn;
    const bool isQ = (blockIdx.x < D_MODEL / GBN);
#pragma unroll
    for (int mi = 0; mi < 4; mi++) {
#pragma unroll
        for (int ni = 0; ni < 4; ni++) {
            const int col = colBase + ni * 8 + 2 * t4;
            const int r0  = rowBase + mi * 16 + g;
            float2 v0, v1;
            v0.x = acc[mi][ni][0] + bias[col];
            v0.y = acc[mi][ni][1] + bias[col + 1];
            v1.x = acc[mi][ni][2] + bias[col];
            v1.y = acc[mi][ni][3] + bias[col + 1];
            if (isQ) {
                *(float2*)&CQ[(size_t)r0 * D_MODEL + col]       = v0;
                *(float2*)&CQ[(size_t)(r0 + 8) * D_MODEL + col] = v1;
            } else {
                const int kc = col - D_MODEL;
                *(float2*)&CKV[(size_t)r0 * KVN + kc]       = v0;
                *(float2*)&CKV[(size_t)(r0 + 8) * KVN + kc] = v1;
            }
        }
    }
}

// ---------------------------------------------------------------------------
// TF32 GEMM (ldmatrix). C = A @ Bt^T + bias.  (O projection, unchanged)
// ---------------------------------------------------------------------------
__global__ __launch_bounds__(256, 2) void tf32_gemm_bias(
    int M, int N, int K,
    const float* __restrict__ A,
    const uint32_t* __restrict__ Bt,
    const float* __restrict__ bias,
    float* __restrict__ C)
{
    __shared__ uint32_t As[GBM * ASTR];
    __shared__ uint32_t Bs[GBN * BSTR2];

    const int tid  = threadIdx.x;
    const int wid  = tid >> 5;
    const int lane = tid & 31;
    const int g    = lane >> 2;
    const int t4   = lane & 3;
    const int wm   = (wid >> 2) * 64;
    const int wn   = (wid & 3) * 32;

    const float*    Ab = A  + (size_t)blockIdx.y * GBM * K;
    const uint32_t* Bb = Bt + (size_t)blockIdx.x * GBN * K;

    const int lrow = tid >> 3;
    const int lcol = (tid & 7) * 4;

    const int a_row = (lane & 7) + ((lane >> 3) & 1) * 8;
    const int a_kh  = ((lane >> 4) & 1) * 4;
    const int b_row = (lane & 7) + ((lane >> 4) & 1) * 8;
    const int b_kh  = ((lane >> 3) & 1) * 4;

    const uint32_t As_b = (uint32_t)__cvta_generic_to_shared(As);
    const uint32_t Bs_b = (uint32_t)__cvta_generic_to_shared(Bs);

    float acc[4][4][4];
#pragma unroll
    for (int mi = 0; mi < 4; mi++)
#pragma unroll
        for (int ni = 0; ni < 4; ni++)
#pragma unroll
            for (int r = 0; r < 4; r++) acc[mi][ni][r] = 0.0f;

    for (int k0 = 0; k0 < K; k0 += GBK) {
#pragma unroll
        for (int i = 0; i < 4; i++) {
            int row = lrow + 32 * i;
            float4 a = *(const float4*)&Ab[(size_t)row * K + k0 + lcol];
            uint4 u = make_uint4(f2tf32(a.x), f2tf32(a.y), f2tf32(a.z), f2tf32(a.w));
            *(uint4*)&As[row * ASTR + lcol] = u;
        }
#pragma unroll
        for (int i = 0; i < 4; i++) {
            int row = lrow + 32 * i;
            uint4 u = *(const uint4*)&Bb[(size_t)row * K + k0 + lcol];
            *(uint4*)&Bs[row * BSTR2 + lcol] = u;
        }
        __syncthreads();

#pragma unroll
        for (int ks = 0; ks < 4; ks++) {
            uint32_t a[4][4];
#pragma unroll
            for (int mi = 0; mi < 4; mi++) {
                uint32_t addr = As_b +
                    ((wm + mi * 16 + a_row) * ASTR + ks * 8 + a_kh) * 4;
                ldsm_x4(a[mi][0], a[mi][1], a[mi][2], a[mi][3], addr);
            }
            uint32_t bf[2][4];
#pragma unroll
            for (int p = 0; p < 2; p++) {
                uint32_t addr = Bs_b +
                    ((wn + p * 16 + b_row) * BSTR2 + ks * 8 + b_kh) * 4;
                ldsm_x4(bf[p][0], bf[p][1], bf[p][2], bf[p][3], addr);
            }
#pragma unroll
            for (int p = 0; p < 2; p++)
#pragma unroll
                for (int hh = 0; hh < 2; hh++) {
                    const int ni = p * 2 + hh;
#pragma unroll
                    for (int mi = 0; mi < 4; mi++)
                        mma_tf32(acc[mi][ni],
                                 a[mi][0], a[mi][1], a[mi][2], a[mi][3],
                                 bf[p][hh * 2], bf[p][hh * 2 + 1]);
                }
        }
        __syncthreads();
    }

    const int rowBase = blockIdx.y * GBM + wm;
    const int colBase = blockIdx.x * GBN + wn;
#pragma unroll
    for (int mi = 0; mi < 4; mi++) {
#pragma unroll
        for (int ni = 0; ni < 4; ni++) {
            const int col = colBase + ni * 8 + 2 * t4;
            const int r0  = rowBase + mi * 16 + g;
            float2 v0, v1;
            v0.x = acc[mi][ni][0] + bias[col];
            v0.y = acc[mi][ni][1] + bias[col + 1];
            v1.x = acc[mi][ni][2] + bias[col];
            v1.y = acc[mi][ni][3] + bias[col + 1];
            *(float2*)&C[(size_t)r0 * N + col]       = v0;
            *(float2*)&C[(size_t)(r0 + 8) * N + col] = v1;
        }
    }
}

// ---------------------------------------------------------------------------
// Convert fused KV output: cols 0..127 -> K tf32 bits [tok][d];
// cols 128..255 -> Vt tf32 bits [d][tok] (transposed via smem tile).
// grid (8, NTOK/32), block (32, 8).
// ---------------------------------------------------------------------------
__global__ __launch_bounds__(256) void kv_convert_t(
    const float* __restrict__ kvf,
    uint32_t* __restrict__ Kout, uint32_t* __restrict__ Vt)
{
    __shared__ float tile[32][33];
    const int col0 = blockIdx.x * 32;
    const int tok0 = blockIdx.y * 32;
    const int tx = threadIdx.x, ty = threadIdx.y;
    const int col = col0 + tx;
    const bool isK = (col0 < HEAD_DIM);

#pragma unroll
    for (int j = 0; j < 32; j += 8) {
        const int tok = tok0 + ty + j;
        float s = kvf[(size_t)tok * KVN + col];
        if (isK) Kout[(size_t)tok * HEAD_DIM + col] = f2tf32(s);
        else     tile[ty + j][tx] = s;
    }
    if (!isK) {
        __syncthreads();
#pragma unroll
        for (int j = 0; j < 32; j += 8)
            Vt[(size_t)(col0 - HEAD_DIM + ty + j) * NTOK + tok0 + tx] =
                f2tf32(tile[tx][ty + j]);
    }
}

// ---------------------------------------------------------------------------
// TF32 MMA flash attention (exact R12): AQ=64, 128 threads, 2 CTAs/SM,
// K register-prefetch, V demand-load, ldmatrix score+PV paths.
// ---------------------------------------------------------------------------
#define AQ 64
#define AK 64
#define QP 132
#define KP 132
#define VP2 68

__global__ __launch_bounds__(128, 2) void mqa_attn_tf32(
    const float* __restrict__ Q,
    const uint32_t* __restrict__ Kg,
    const uint32_t* __restrict__ Vtg,
    const int* __restrict__ mask,
    float* __restrict__ Og)
{
    extern __shared__ uint32_t sm_u[];
    uint32_t* Qs   = sm_u;
    uint32_t* Ks   = Qs + AQ * QP;
    uint32_t* Vts  = Ks + AK * KP;
    float*   sbias = (float*)(Vts + HEAD_DIM * VP2);

    const int tid  = threadIdx.x;
    const int wid  = tid >> 5;
    const int lane = tid & 31;
    const int g    = lane >> 2;
    const int t4   = lane & 3;
    const int b  = blockIdx.z, h = blockIdx.y;
    const int q0 = blockIdx.x * AQ;
    const int wrow = wid * 16;

    const int a_row = (lane & 7) + ((lane >> 3) & 1) * 8;
    const int a_kh  = ((lane >> 4) & 1) * 4;
    const int b_row = (lane & 7) + ((lane >> 4) & 1) * 8;
    const int b_kh  = ((lane >> 3) & 1) * 4;
    const uint32_t Qs_b  = (uint32_t)__cvta_generic_to_shared(Qs);
    const uint32_t Ks_b  = (uint32_t)__cvta_generic_to_shared(Ks);
    const uint32_t Vts_b = (uint32_t)__cvta_generic_to_shared(Vts);

    const uint32_t* Kgb  = Kg  + (size_t)(b * SEQ) * HEAD_DIM;
    const uint32_t* Vtgb = Vtg + (size_t)b * SEQ;

    const int kpr = tid >> 5;
    const int kpc = (tid & 31) << 2;
    const int vpr = tid >> 4;
    const int vpc = (tid & 15) << 2;

    const float* Qp = Q + ((size_t)(b * SEQ + q0)) * D_MODEL + h * HEAD_DIM;
    for (int i = tid; i < AQ * HEAD_DIM / 4; i += 128) {
        int r = i >> 5, c = (i & 31) << 2;
        float4 qv = *(const float4*)&Qp[(size_t)r * D_MODEL + c];
        uint4 u = make_uint4(f2tf32(qv.x), f2tf32(qv.y), f2tf32(qv.z), f2tf32(qv.w));
        *(uint4*)&Qs[r * QP + c] = u;
    }

    uint4 kreg[16];
#pragma unroll
    for (int u = 0; u < 16; u++)
        kreg[u] = *(const uint4*)&Kgb[(size_t)(kpr + 4 * u) * HEAD_DIM + kpc];

    float m0 = -1e30f, m1 = -1e30f, l0 = 0.0f, l1 = 0.0f;
    float o[16][4];
#pragma unroll
    for (int n = 0; n < 16; n++)
#pragma unroll
        for (int r = 0; r < 4; r++) o[n][r] = 0.0f;

    const float scale = 0.08838834764831845f;

    for (int k0 = 0; k0 < SEQ; k0 += AK) {
        __syncthreads();
#pragma unroll
        for (int u = 0; u < 16; u++)
            *(uint4*)&Ks[(kpr + 4 * u) * KP + kpc] = kreg[u];
#pragma unroll
        for (int u = 0; u < 16; u++)
            *(uint4*)&Vts[(vpr + 8 * u) * VP2 + vpc] =
                *(const uint4*)&Vtgb[(size_t)(vpr + 8 * u) * NTOK + k0 + vpc];
        if (tid < AK)
            sbias[tid] = mask[(size_t)b * SEQ + k0 + tid] ? 0.0f : -1e9f;
        __syncthreads();

        if (k0 + AK < SEQ) {
            const uint32_t* Kp = Kgb + (size_t)(k0 + AK) * HEAD_DIM;
#pragma unroll
            for (int u = 0; u < 16; u++)
                kreg[u] = *(const uint4*)&Kp[(size_t)(kpr + 4 * u) * HEAD_DIM + kpc];
        }

        float s[8][4];
#pragma unroll
        for (int j = 0; j < 8; j++)
#pragma unroll
            for (int r = 0; r < 4; r++) s[j][r] = 0.0f;

#pragma unroll
        for (int ks = 0; ks < 16; ks++) {
            uint32_t aq[4];
            ldsm_x4(aq[0], aq[1], aq[2], aq[3],
                    Qs_b + ((wrow + a_row) * QP + ks * 8 + a_kh) * 4);
#pragma unroll
            for (int p = 0; p < 4; p++) {
                uint32_t bf[4];
                ldsm_x4(bf[0], bf[1], bf[2], bf[3],
                        Ks_b + ((p * 16 + b_row) * KP + ks * 8 + b_kh) * 4);
                mma_tf32(s[2 * p],     aq[0], aq[1], aq[2], aq[3], bf[0], bf[1]);
                mma_tf32(s[2 * p + 1], aq[0], aq[1], aq[2], aq[3], bf[2], bf[3]);
            }
        }

        float rmax0 = -1e30f, rmax1 = -1e30f;
#pragma unroll
        for (int j = 0; j < 8; j++) {
            float2 sv = *(float2*)&sbias[j * 8 + 2 * t4];
            s[j][0] = s[j][0] * scale + sv.x;
            s[j][1] = s[j][1] * scale + sv.y;
            s[j][2] = s[j][2] * scale + sv.x;
            s[j][3] = s[j][3] * scale + sv.y;
            rmax0 = fmaxf(rmax0, fmaxf(s[j][0], s[j][1]));
            rmax1 = fmaxf(rmax1, fmaxf(s[j][2], s[j][3]));
        }
#pragma unroll
        for (int off = 1; off <= 2; off <<= 1) {
            rmax0 = fmaxf(rmax0, __shfl_xor_sync(0xffffffffu, rmax0, off));
            rmax1 = fmaxf(rmax1, __shfl_xor_sync(0xffffffffu, rmax1, off));
        }
        const float mn0 = fmaxf(m0, rmax0);
        const float mn1 = fmaxf(m1, rmax1);
        const float c0 = __expf(m0 - mn0);
        const float c1 = __expf(m1 - mn1);
        m0 = mn0; m1 = mn1;

        float rs0 = 0.0f, rs1 = 0.0f;
        uint32_t pt[8][4];
#pragma unroll
        for (int j = 0; j < 8; j++) {
            float p0 = __expf(s[j][0] - mn0);
            float p1 = __expf(s[j][1] - mn0);
            float p2 = __expf(s[j][2] - mn1);
            float p3 = __expf(s[j][3] - mn1);
            rs0 += p0 + p1;
            rs1 += p2 + p3;
            pt[j][0] = f2tf32(p0);
            pt[j][1] = f2tf32(p1);
            pt[j][2] = f2tf32(p2);
            pt[j][3] = f2tf32(p3);
        }
#pragma unroll
        for (int off = 1; off <= 2; off <<= 1) {
            rs0 += __shfl_xor_sync(0xffffffffu, rs0, off);
            rs1 += __shfl_xor_sync(0xffffffffu, rs1, off);
        }
        l0 = l0 * c0 + rs0;
        l1 = l1 * c1 + rs1;

#pragma unroll
        for (int n = 0; n < 16; n++) {
            o[n][0] *= c0; o[n][1] *= c0;
            o[n][2] *= c1; o[n][3] *= c1;
        }

        const int src1 = (g << 2) + (t4 >> 1);
        const int src2 = src1 + 2;
        const bool odd = (t4 & 1);
#pragma unroll
        for (int j = 0; j < 8; j++) {
            uint32_t x00 = __shfl_sync(0xffffffffu, pt[j][0], src1);
            uint32_t x01 = __shfl_sync(0xffffffffu, pt[j][1], src1);
            uint32_t x10 = __shfl_sync(0xffffffffu, pt[j][0], src2);
            uint32_t x11 = __shfl_sync(0xffffffffu, pt[j][1], src2);
            uint32_t x20 = __shfl_sync(0xffffffffu, pt[j][2], src1);
            uint32_t x21 = __shfl_sync(0xffffffffu, pt[j][3], src1);
            uint32_t x30 = __shfl_sync(0xffffffffu, pt[j][2], src2);
            uint32_t x31 = __shfl_sync(0xffffffffu, pt[j][3], src2);
            uint32_t a0 = odd ? x01 : x00;
            uint32_t a2 = odd ? x11 : x10;
            uint32_t a1 = odd ? x21 : x20;
            uint32_t a3 = odd ? x31 : x30;
#pragma unroll
            for (int p = 0; p < 8; p++) {
                uint32_t bf[4];
                ldsm_x4(bf[0], bf[1], bf[2], bf[3],
                        Vts_b + ((p * 16 + b_row) * VP2 + j * 8 + b_kh) * 4);
                mma_tf32(o[2 * p],     a0, a1, a2, a3, bf[0], bf[1]);
                mma_tf32(o[2 * p + 1], a0, a1, a2, a3, bf[2], bf[3]);
            }
        }
    }

    const float inv0 = 1.0f / l0;
    const float inv1 = 1.0f / l1;
    float* Op0 = Og + ((size_t)(b * SEQ + q0 + wrow + g    )) * D_MODEL + h * HEAD_DIM;
    float* Op1 = Og + ((size_t)(b * SEQ + q0 + wrow + g + 8)) * D_MODEL + h * HEAD_DIM;
#pragma unroll
    for (int n = 0; n < 16; n++) {
        const int col = n * 8 + 2 * t4;
        float2 v0, v1;
        v0.x = o[n][0] * inv0; v0.y = o[n][1] * inv0;
        v1.x = o[n][2] * inv1; v1.y = o[n][3] * inv1;
        *(float2*)&Op0[col] = v0;
        *(float2*)&Op1[col] = v1;
    }
}

#define ATTN_SMEM_BYTES ((AQ * QP + AK * KP + HEAD_DIM * VP2) * 4 + AK * 4)

// ---------------------------------------------------------------------------
extern "C" void kernel_launch(void* const* d_in, const int* in_sizes, int n_in,
                              void* d_out, int out_size)
{
    const float* x    = (const float*)d_in[0];
    const int*   mask = (const int*)d_in[1];
    const float* Wq   = (const float*)d_in[2];
    const float* bq   = (const float*)d_in[3];
    const float* Wk   = (const float*)d_in[4];
    const float* bk   = (const float*)d_in[5];
    const float* Wv   = (const float*)d_in[6];
    const float* bv   = (const float*)d_in[7];
    const float* Wo   = (const float*)d_in[8];
    const float* bo   = (const float*)d_in[9];
    float* out = (float*)d_out;

    float *q, *kvf, *ao, *bqkv;
    uint32_t *kt, *vt, *wqkvt, *wot;
    cudaGetSymbolAddress((void**)&q,     g_q);
    cudaGetSymbolAddress((void**)&kvf,   g_kvf);
    cudaGetSymbolAddress((void**)&kt,    g_kt);
    cudaGetSymbolAddress((void**)&vt,    g_vt);
    cudaGetSymbolAddress((void**)&ao,    g_ao);
    cudaGetSymbolAddress((void**)&wqkvt, g_wqkvt);
    cudaGetSymbolAddress((void**)&wot,   g_wot);
    cudaGetSymbolAddress((void**)&bqkv,  g_bqkv);

    // Weight transposes (tf32) into fused Wqkv^T + Wo^T; combined bias
    transpose_kn<<<dim3(64, 64), dim3(32, 8)>>>(Wq, wqkvt, D_MODEL, 0);
    transpose_kn<<<dim3(4, 64),  dim3(32, 8)>>>(Wk, wqkvt, HEAD_DIM, D_MODEL);
    transpose_kn<<<dim3(4, 64),  dim3(32, 8)>>>(Wv, wqkvt, HEAD_DIM, D_MODEL + HEAD_DIM);
    transpose_kn<<<dim3(64, 64), dim3(32, 8)>>>(Wo, wot, D_MODEL, 0);
    build_bias<<<(NQKV + 255) / 256, 256>>>(bq, bk, bv, bqkv);

    // Fused QKV projection (one launch, 576 blocks)
    qkv_gemm_fused<<<dim3(NQKV / GBN, NTOK / GBM), 256>>>(x, wqkvt, bqkv, q, kvf);

    // Convert K -> tf32 bits, V -> transposed tf32 bits
    kv_convert_t<<<dim3(KVN / 32, NTOK / 32), dim3(32, 8)>>>(kvf, kt, vt);

    // Attention (exact R12)
    cudaFuncSetAttribute(mqa_attn_tf32,
                         cudaFuncAttributeMaxDynamicSharedMemorySize,
                         ATTN_SMEM_BYTES);
    mqa_attn_tf32<<<dim3(SEQ / AQ, N_HEADS, BATCH), 128, ATTN_SMEM_BYTES>>>(
        q, kt, vt, mask, ao);

    // Output projection
    tf32_gemm_bias<<<dim3(D_MODEL / GBN, NTOK / GBM), 256>>>(
        NTOK, D_MODEL, D_MODEL, ao, wot, bo, out);
}